// round 2
// baseline (speedup 1.0000x reference)
#include <cuda_runtime.h>
#include <cstdint>

typedef unsigned long long u64;

#define HW 3136  // 56*56

// Intermediate T[l][m][n][i*4+j] : (128, 56, 56, 8) floats = 12.85 MB scratch
__device__ float g_T[128 * 56 * 56 * 8];

__device__ __forceinline__ u64 pack2(float a, float b) {
    u64 r; asm("mov.b64 %0, {%1,%2};" : "=l"(r) : "f"(a), "f"(b)); return r;
}
__device__ __forceinline__ float2 unpack2(u64 a) {
    float2 r; asm("mov.b64 {%0,%1}, %2;" : "=f"(r.x), "=f"(r.y) : "l"(a)); return r;
}
__device__ __forceinline__ u64 fma2(u64 a, u64 b, u64 c) {
    u64 d; asm("fma.rn.f32x2 %0, %1, %2, %3;" : "=l"(d) : "l"(a), "l"(b), "l"(c)); return d;
}

// ---------------------------------------------------------------------------
// K1: T[l,m,w, i*4+j] = sum_{kk<64, tap<3, valid} x[l, 2kk+i, rowof(m+tap-1), w] * w1[kk,tap,j]
//   rowof(hp) = (hp<=0) ? 55 : hp-1   (the +1 circular roll), contribution 0 if hp outside [0,56)
//
// Thread = (l, mq: 4-row m chunk, wq: 4-wide w quad, i, jh: j pair).
// Each thread loads 6 source rows per (kk) ONCE and applies to all (mi,tap) with s=mi+tap.
// 100,352 threads = 392 blocks x 256.  Packed f32x2 FMA over w pairs.
// ---------------------------------------------------------------------------
__global__ __launch_bounds__(256) void k1_stage1(const float* __restrict__ x,
                                                 const float* __restrict__ w1) {
    __shared__ float w1s[64 * 12];   // [kk*12 + tap*4 + j]
    int tid = threadIdx.x;
    for (int idx = tid; idx < 768; idx += 256) w1s[idx] = w1[idx];
    __syncthreads();

    int gt  = blockIdx.x * 256 + tid;
    int jh  = gt & 1;
    int i   = (gt >> 1) & 1;
    int wq  = (gt >> 2) % 14;
    int rem = gt / 56;
    int mq  = rem % 14;
    int l   = rem / 14;
    int m0  = mq * 4;
    int w0  = wq * 4;

    // rows + validity for hp = m0-1 .. m0+4  (s = 0..5)
    int  rows[6];
    bool val[6];
#pragma unroll
    for (int s = 0; s < 6; s++) {
        int hp  = m0 - 1 + s;
        val[s]  = (hp >= 0) && (hp < 56);
        rows[s] = (hp <= 0) ? 55 : ((hp >= 56) ? 55 : hp - 1);  // clamped safe index
    }

    u64 acc[4][2][2];  // [mi][jl][wp]
#pragma unroll
    for (int mi = 0; mi < 4; mi++)
#pragma unroll
        for (int jl = 0; jl < 2; jl++)
#pragma unroll
            for (int wp = 0; wp < 2; wp++) acc[mi][jl][wp] = 0ull;

    const float* xb = x + ((size_t)l * 128 + i) * HW + w0;

#pragma unroll 2
    for (int kk = 0; kk < 64; kk++) {
        const float* cb = xb + (size_t)(2 * kk) * HW;

        // packed weights (w,w) for this thread's 2 j values
        u64 W[3][2];
#pragma unroll
        for (int tap = 0; tap < 3; tap++) {
            float2 wv = *reinterpret_cast<const float2*>(&w1s[kk * 12 + tap * 4 + jh * 2]);
            W[tap][0] = pack2(wv.x, wv.x);
            W[tap][1] = pack2(wv.y, wv.y);
        }

        // load all 6 rows once (addresses always in-bounds; invalid ones unused)
        u64 xr[6][2];
#pragma unroll
        for (int s = 0; s < 6; s++) {
            ulonglong2 v = *reinterpret_cast<const ulonglong2*>(cb + rows[s] * 56);
            xr[s][0] = v.x;
            xr[s][1] = v.y;
        }

#pragma unroll
        for (int mi = 0; mi < 4; mi++) {
#pragma unroll
            for (int tap = 0; tap < 3; tap++) {
                int s = mi + tap;
                if (val[s]) {
#pragma unroll
                    for (int jl = 0; jl < 2; jl++) {
                        acc[mi][jl][0] = fma2(xr[s][0], W[tap][jl], acc[mi][jl][0]);
                        acc[mi][jl][1] = fma2(xr[s][1], W[tap][jl], acc[mi][jl][1]);
                    }
                }
            }
        }
    }

    // store: T[(l,m,w)*8 + i*4 + jh*2 + jl], one float2 (jl0,jl1) per (mi, w)
#pragma unroll
    for (int mi = 0; mi < 4; mi++) {
        float* Tp = g_T + (((size_t)l * 56 + (m0 + mi)) * 56 + w0) * 8 + i * 4 + jh * 2;
#pragma unroll
        for (int wp = 0; wp < 2; wp++) {
            float2 a0 = unpack2(acc[mi][0][wp]);  // jl=0, (w even, w odd)
            float2 a1 = unpack2(acc[mi][1][wp]);  // jl=1
            *reinterpret_cast<float2*>(Tp + (2 * wp + 0) * 8) = make_float2(a0.x, a1.x);
            *reinterpret_cast<float2*>(Tp + (2 * wp + 1) * 8) = make_float2(a0.y, a1.y);
        }
    }
}

// ---------------------------------------------------------------------------
// K2: out[l, 4j+oo, m, n] = sum_{i2<2,k<3} T[l,m,n+k-1, i2*4+oo] * w2[i2,k,j]
// Thread = (l, m, n pair, jg: 8 j values). 802,816 threads = 3584 blocks x 224.
// T rows load as ulonglong2 -> halves are natural (oo0,oo1)/(oo2,oo3) f32x2 pairs.
// ---------------------------------------------------------------------------
__global__ __launch_bounds__(224) void k2_stage2(const float* __restrict__ w2,
                                                 float* __restrict__ out) {
    __shared__ float w2s[192];   // [i2*96 + k*32 + j]
    int tid = threadIdx.x;
    if (tid < 192) w2s[tid] = w2[tid];
    __syncthreads();

    int np2  = tid % 28;         // n pair index
    int jg   = (tid / 28) % 4;   // j group of 8
    int mloc = tid / 112;        // 0..1
    int m    = blockIdx.x * 2 + mloc;
    int l    = blockIdx.y;
    int n0   = np2 * 2;

    // load 4 T positions: np = n0-1 .. n0+2, each row = 8 floats = 2 x ulonglong2
    ulonglong2 tvp[4][2];        // [s][i2] ; .x=(oo0,oo1) .y=(oo2,oo3)
    const float* Tp = g_T + (((size_t)l * 56 + m) * 56) * 8;
#pragma unroll
    for (int s = 0; s < 4; s++) {
        int np = n0 - 1 + s;
        if (np >= 0 && np < 56) {
            tvp[s][0] = *reinterpret_cast<const ulonglong2*>(Tp + np * 8);
            tvp[s][1] = *reinterpret_cast<const ulonglong2*>(Tp + np * 8 + 4);
        } else {
            tvp[s][0] = make_ulonglong2(0ull, 0ull);
            tvp[s][1] = make_ulonglong2(0ull, 0ull);
        }
    }

    float* ob = out + (size_t)l * 128 * HW + m * 56 + n0;

#pragma unroll
    for (int jl = 0; jl < 8; jl++) {
        int j = jg * 8 + jl;

        u64 wv[2][3];
#pragma unroll
        for (int i2 = 0; i2 < 2; i2++)
#pragma unroll
            for (int k = 0; k < 3; k++) {
                float w = w2s[i2 * 96 + k * 32 + j];
                wv[i2][k] = pack2(w, w);
            }

        u64 rrp[2][2];  // [oh][nn]
        rrp[0][0] = rrp[0][1] = rrp[1][0] = rrp[1][1] = 0ull;
#pragma unroll
        for (int nn = 0; nn < 2; nn++)
#pragma unroll
            for (int i2 = 0; i2 < 2; i2++)
#pragma unroll
                for (int k = 0; k < 3; k++) {
                    int s = nn + k;
                    rrp[0][nn] = fma2(tvp[s][i2].x, wv[i2][k], rrp[0][nn]);
                    rrp[1][nn] = fma2(tvp[s][i2].y, wv[i2][k], rrp[1][nn]);
                }

        float2 r00 = unpack2(rrp[0][0]);  // (oo0,oo1) at n0
        float2 r01 = unpack2(rrp[0][1]);  // (oo0,oo1) at n0+1
        float2 r10 = unpack2(rrp[1][0]);  // (oo2,oo3) at n0
        float2 r11 = unpack2(rrp[1][1]);  // (oo2,oo3) at n0+1

        *reinterpret_cast<float2*>(ob + (size_t)(4 * j + 0) * HW) = make_float2(r00.x, r01.x);
        *reinterpret_cast<float2*>(ob + (size_t)(4 * j + 1) * HW) = make_float2(r00.y, r01.y);
        *reinterpret_cast<float2*>(ob + (size_t)(4 * j + 2) * HW) = make_float2(r10.x, r11.x);
        *reinterpret_cast<float2*>(ob + (size_t)(4 * j + 3) * HW) = make_float2(r10.y, r11.y);
    }
}

// ---------------------------------------------------------------------------
extern "C" void kernel_launch(void* const* d_in, const int* in_sizes, int n_in,
                              void* d_out, int out_size) {
    const float* x  = nullptr;
    const float* w1 = nullptr;
    const float* w2 = nullptr;
    for (int i = 0; i < n_in; i++) {
        if (in_sizes[i] == 128 * 128 * 56 * 56) x  = (const float*)d_in[i];
        else if (in_sizes[i] == 64 * 3 * 4)     w1 = (const float*)d_in[i];
        else if (in_sizes[i] == 2 * 3 * 32)     w2 = (const float*)d_in[i];
    }
    if (!x)  x  = (const float*)d_in[0];
    if (!w1) w1 = (const float*)d_in[1];
    if (!w2) w2 = (const float*)d_in[2];

    k1_stage1<<<392, 256>>>(x, w1);
    k2_stage2<<<dim3(28, 128), 224>>>(w2, (float*)d_out);
}